// round 15
// baseline (speedup 1.0000x reference)
#include <cuda_runtime.h>
#include <cuda_fp16.h>
#include <cstdint>

// ---------------------------------------------------------------------------
// out[i,n] = elu( sum_{c,y,x} conv[i,c,y,x] * Wc[n,c]*Wy[n,y]*Wx[n,x] + bias[n] )
// s[(i,c), n] = conv_flat[16384 x 1296] @ Wyx[8192 x 1296]^T   (fp16 HMMA, f32 acc)
// R15: BM=128 x BN=256, 512 thr / 16 warps (warp tile 64x32), 1 CTA/SM,
// barrier-free 3-stage bulk+mbarrier ring. Bytes/MMA 256 -> 234 (crossbar
// demand 117 B/cyc < 128 cap) while keeping 4 warps/SMSP issue density.
// Partial last k-tile + lane0 empty-arrives kept from R14.
// tcgen05 unavailable: harness PTX target is sm_103 (no 'a' suffix).
// ---------------------------------------------------------------------------
#define MDIM 16384
#define NDIM 8192
#define KDIM 1296
#define KP   1344            // 21 * 64
#define NT   21
#define BM   128
#define BN   256
#define BK   64              // 64 halfs = 128B rows (SW128 atom)

#define A_TILE_BYTES (BM * BK * 2)                   // 16384
#define B_TILE_BYTES (BN * BK * 2)                   // 32768
#define STAGE_BYTES  (A_TILE_BYTES + B_TILE_BYTES)   // 49152
#define SMEM_BARS  (3 * STAGE_BYTES)                 // 147456: full[3]@+0, empty[3]@+24
#define SMEM_WCH   (SMEM_BARS + 64)                  // 147520: 256 x 66 half
#define WC_PITCH   66
#define SMEM_TOTAL (SMEM_WCH + BN * WC_PITCH * 2)    // 181312 (1 CTA <= 227KB)

// Pre-swizzled, tile-contiguous operand images (device globals: no-alloc rule)
__device__ __align__(1024) unsigned char g_A_t[(size_t)(MDIM / BM) * NT * A_TILE_BYTES]; // 44 MB
__device__ __align__(1024) unsigned char g_B_t[(size_t)(NDIM / BN) * NT * B_TILE_BYTES]; // 22 MB
__device__ int g_probe_sink;

// ---------------------------------------------------------------------------
__device__ __forceinline__ uint32_t smem_u32(const void* p) {
    uint32_t a;
    asm("{ .reg .u64 t; cvta.to.shared.u64 t, %1; cvt.u32.u64 %0, t; }" : "=r"(a) : "l"(p));
    return a;
}
__device__ __forceinline__ void bulk_ld(uint32_t dst, const void* src,
                                        uint32_t bytes, uint32_t mbar) {
    asm volatile(
        "cp.async.bulk.shared::cta.global.mbarrier::complete_tx::bytes [%0], [%1], %2, [%3];"
        :: "r"(dst), "l"(src), "r"(bytes), "r"(mbar) : "memory");
}
#define MBAR_INIT(a, n) \
    asm volatile("mbarrier.init.shared.b64 [%0], %1;" :: "r"(a), "r"((uint32_t)(n)) : "memory")
#define MBAR_ARRIVE(a) \
    asm volatile("mbarrier.arrive.shared.b64 _, [%0];" :: "r"(a) : "memory")
#define MBAR_EXPECT_TX(a, b) \
    asm volatile("mbarrier.arrive.expect_tx.shared.b64 _, [%0], %1;" \
                 :: "r"(a), "r"((uint32_t)(b)) : "memory")
#define MBAR_WAIT(a, ph) do {                                                        \
    asm volatile("{\n\t.reg .pred P;\n\t"                                            \
        "W%=:\n\t"                                                                   \
        "mbarrier.try_wait.parity.acquire.cta.shared::cta.b64 P, [%0], %1, 0x989680;\n\t" \
        "@P bra.uni D%=;\n\t bra.uni W%=;\n\tD%=:\n\t}"                              \
        :: "r"(a), "r"((uint32_t)(ph)) : "memory");                                  \
} while (0)

#define LDSM4(R0, R1, R2, R3, ADDR)                                            \
    asm volatile("ldmatrix.sync.aligned.m8n8.x4.shared.b16 {%0,%1,%2,%3}, [%4];" \
                 : "=r"(R0), "=r"(R1), "=r"(R2), "=r"(R3) : "r"(ADDR))

#define MMA16816(D, A, B)                                                      \
    asm volatile("mma.sync.aligned.m16n8k16.row.col.f32.f16.f16.f32 "          \
                 "{%0,%1,%2,%3}, {%4,%5,%6,%7}, {%8,%9}, {%0,%1,%2,%3};"       \
                 : "+f"((D)[0]), "+f"((D)[1]), "+f"((D)[2]), "+f"((D)[3])      \
                 : "r"((A)[0]), "r"((A)[1]), "r"((A)[2]), "r"((A)[3]),         \
                   "r"((B)[0]), "r"((B)[1]))

// ---------------------------------------------------------------------------
__global__ void probe_kernel() { g_probe_sink = 1; }   // ncu slot #4 -> GEMM

// ---------------------------------------------------------------------------
// Prep A: conv fp32 -> fp16, tiled + SW128-swizzled image, K padded to 1344
// ---------------------------------------------------------------------------
__global__ void prepA_kernel(const float* __restrict__ conv) {
    int g = blockIdx.x * 256 + threadIdx.x;
    if (g >= MDIM * (KP / 8)) return;
    int m  = g / (KP / 8);
    int k0 = (g - m * (KP / 8)) * 8;

    __half2 h[4];
    if (k0 < KDIM) {   // 1296 = 162*8 -> granules fully in or out
        const float4* s = (const float4*)(conv + (size_t)m * KDIM + k0);
        float4 a = s[0], b = s[1];
        h[0] = __floats2half2_rn(a.x, a.y);
        h[1] = __floats2half2_rn(a.z, a.w);
        h[2] = __floats2half2_rn(b.x, b.y);
        h[3] = __floats2half2_rn(b.z, b.w);
    } else {
        h[0] = h[1] = h[2] = h[3] = __floats2half2_rn(0.f, 0.f);
    }
    int tm = m >> 7, row = m & 127, kt = k0 >> 6, kc = k0 & 63;
    uint32_t off = row * 128 + kc * 2;
    uint32_t sw  = off ^ ((off >> 3) & 0x70);
    *(uint4*)(g_A_t + (size_t)(tm * NT + kt) * A_TILE_BYTES + sw) = *(uint4*)h;
}

// ---------------------------------------------------------------------------
// Prep B: Wyx[n, y*36+x] = Wy[n,y]*Wx[n,x] -> fp16 tiled swizzled image (BN=256)
// ---------------------------------------------------------------------------
__global__ void prepB_kernel(const float* __restrict__ Wy, const float* __restrict__ Wx) {
    int g = blockIdx.x * 256 + threadIdx.x;
    if (g >= NDIM * (KP / 8)) return;
    int n  = g / (KP / 8);
    int k0 = (g - n * (KP / 8)) * 8;

    __half hv[8];
    if (k0 < KDIM) {
#pragma unroll
        for (int j = 0; j < 8; j++) {
            int k = k0 + j;
            int y = k / 36, x = k - y * 36;
            hv[j] = __float2half(Wy[n * 36 + y] * Wx[n * 36 + x]);
        }
    } else {
#pragma unroll
        for (int j = 0; j < 8; j++) hv[j] = __float2half(0.f);
    }
    int tn = n >> 8, row = n & 255, kt = k0 >> 6, kc = k0 & 63;
    uint32_t off = row * 128 + kc * 2;
    uint32_t sw  = off ^ ((off >> 3) & 0x70);
    *(uint4*)(g_B_t + (size_t)(tn * NT + kt) * B_TILE_BYTES + sw) = *(uint4*)hv;
}

// ---------------------------------------------------------------------------
// Fused GEMM: 128x256x64 tiles, 16 warps (warp tile 64x32, 2x8 grid),
// mbarrier-ringed 3-stage cp.async.bulk pipeline, 1 CTA/SM, A-frag dbuf,
// partial last k-tile, fused Wc(fp16 smem) reduce + bias(gmem) + ELU.
// ---------------------------------------------------------------------------
__global__ void __launch_bounds__(512, 1) gemm_fused_kernel(
    const float* __restrict__ Wc, const float* __restrict__ bias,
    float* __restrict__ out)
{
    extern __shared__ unsigned char smem[];
    const uint32_t sbase = smem_u32(smem);
    const int tid = threadIdx.x, lane = tid & 31, wid = tid >> 5;
    const int wm = wid >> 3, wn = wid & 7;       // 2 x 8 warp grid, tile 64x32
    const int m_tile = blockIdx.y, n_tile = blockIdx.x;
    const int n0 = n_tile * BN;

    const uint32_t FULLB  = sbase + SMEM_BARS;        // full[s]  at +s*8 (count 1, tx)
    const uint32_t EMPTYB = sbase + SMEM_BARS + 24;   // empty[s] at +s*8 (count 16)

    if (tid == 0) {
#pragma unroll
        for (int s = 0; s < 3; s++) {
            MBAR_INIT(FULLB + s * 8, 1);
            MBAR_INIT(EMPTYB + s * 8, 16);    // one arrive per warp (lane 0)
        }
    }

    // ---- Wc fp32 -> fp16 smem [n][c], pitch 66 ----
#pragma unroll
    for (int it = 0; it < 8; it++) {
        int idx = it * 512 + tid;              // 4096 float4 groups
        int n = idx >> 4, c4 = (idx & 15) * 4;
        float4 v = *(const float4*)(Wc + (size_t)(n0 + n) * 64 + c4);
        __half2* d = (__half2*)(smem + SMEM_WCH + (n * WC_PITCH + c4) * 2);
        d[0] = __floats2half2_rn(v.x, v.y);
        d[1] = __floats2half2_rn(v.z, v.w);
    }
    __syncthreads();   // mbarrier init + Wc visible (only sync in kernel)

#define ISSUE_STAGE(KT, BUF) do {                                              \
    uint32_t d_ = sbase + (BUF) * STAGE_BYTES;                                 \
    uint32_t f_ = FULLB + (BUF) * 8;                                           \
    MBAR_EXPECT_TX(f_, STAGE_BYTES);                                           \
    bulk_ld(d_, g_A_t + ((size_t)m_tile * NT + (KT)) * A_TILE_BYTES,           \
            A_TILE_BYTES, f_);                                                 \
    bulk_ld(d_ + A_TILE_BYTES,                                                 \
            g_B_t + ((size_t)n_tile * NT + (KT)) * B_TILE_BYTES,               \
            B_TILE_BYTES, f_);                                                 \
} while (0)

    if (tid == 0) {
        ISSUE_STAGE(0, 0);
        ISSUE_STAGE(1, 1);
        ISSUE_STAGE(2, 2);
    }

    // ---- merged per-lane ldmatrix constants (SW128) ----
    uint32_t aro[4];
#pragma unroll
    for (int mt = 0; mt < 4; mt++) {
        int r = wm * 64 + mt * 16 + (lane & 15);
        aro[mt] = (uint32_t)(r * 128) ^ ((r & 7) << 4);
    }
    const uint32_t a_colhi = (lane >> 4) * 16;
    const int brow = wn * 32 + lane;             // 32 B-rows per warp
    const uint32_t bro = (uint32_t)(A_TILE_BYTES + brow * 128) ^ ((brow & 7) << 4);

    float acc[4][4][4];
#pragma unroll
    for (int a = 0; a < 4; a++)
#pragma unroll
        for (int b = 0; b < 4; b++)
#pragma unroll
            for (int c = 0; c < 4; c++) acc[a][b][c] = 0.f;

    uint32_t afr[2][4][4];   // A fragments, ks-level double buffer
    uint32_t bfr[4][2];      // B fragments, single buffer

#define LOAD_A(KS, SB, FB) do {                                                \
    const uint32_t colA_ = (KS) * 32 + a_colhi;                                \
    _Pragma("unroll")                                                          \
    for (int mt_ = 0; mt_ < 4; mt_++)                                          \
        LDSM4(afr[FB][mt_][0], afr[FB][mt_][1],                                \
              afr[FB][mt_][2], afr[FB][mt_][3],                                \
              (SB) + (aro[mt_] ^ colA_));                                      \
} while (0)

#define LOAD_B(KS, SB) do {                                                    \
    const uint32_t colB_ = (KS) * 32;                                          \
    uint32_t r0_, r1_, r2_, r3_;                                               \
    LDSM4(r0_, r1_, r2_, r3_, (SB) + (bro ^ colB_));                           \
    bfr[0][0] = r0_; bfr[1][0] = r1_; bfr[2][0] = r2_; bfr[3][0] = r3_;        \
    LDSM4(r0_, r1_, r2_, r3_, (SB) + (bro ^ (colB_ + 16)));                    \
    bfr[0][1] = r0_; bfr[1][1] = r1_; bfr[2][1] = r2_; bfr[3][1] = r3_;        \
} while (0)

#define COMPUTE_TILE(BUF) do {                                                 \
    const uint32_t sb_ = sbase + (BUF) * STAGE_BYTES;                          \
    LOAD_A(0, sb_, 0);                                                         \
    _Pragma("unroll")                                                          \
    for (int ks = 0; ks < 4; ks++) {                                           \
        LOAD_B(ks, sb_);                                                       \
        if (ks < 3) LOAD_A(ks + 1, sb_, (ks + 1) & 1);                         \
        const int cb_ = ks & 1;                                                \
        _Pragma("unroll")                                                      \
        for (int mt = 0; mt < 4; mt++)                                         \
            _Pragma("unroll")                                                  \
            for (int nt = 0; nt < 4; nt++)                                     \
                MMA16816(acc[mt][nt], afr[cb_][mt], bfr[nt]);                  \
    }                                                                          \
} while (0)

// TILE: wait full -> compute -> lane0 releases empty -> (tid0) refill ring
#define TILE(BUF, FPAR, DOREFILL, RBUF, RPAR, RKT) do {                        \
    MBAR_WAIT(FULLB + (BUF) * 8, FPAR);                                        \
    COMPUTE_TILE(BUF);                                                         \
    if (lane == 0) MBAR_ARRIVE(EMPTYB + (BUF) * 8);                            \
    if ((DOREFILL) && tid == 0) {                                              \
        MBAR_WAIT(EMPTYB + (RBUF) * 8, RPAR);                                  \
        ISSUE_STAGE(RKT, RBUF);                                                \
    }                                                                          \
} while (0)

    // ---- mainloop: 20 full tiles + 1 partial (only ks=0 has real data) ----
    int ph = 0;
#pragma unroll 1
    for (int base = 0; base < 18; base += 3, ph ^= 1) {
        TILE(0, ph, (base > 0), 2, ph ^ 1, base + 2);
        TILE(1, ph, true,       0, ph,     base + 3);
        TILE(2, ph, true,       1, ph,     base + 4);
    }
    // peeled final group (base = 18, parity 0)
    TILE(0, 0, true, 2, 1, 20);     // tile 18; refills buf2 with tile 20
    TILE(1, 0, false, 0, 0, 0);     // tile 19; no refill
    {
        // tile 20 (buf 2, parity 0): only ks=0 (k-cols 1280-1295) is real.
        MBAR_WAIT(FULLB + 2 * 8, 0);
        const uint32_t sb_ = sbase + 2 * STAGE_BYTES;
        LOAD_A(0, sb_, 0);
        LOAD_B(0, sb_);
#pragma unroll
        for (int mt = 0; mt < 4; mt++)
#pragma unroll
            for (int nt = 0; nt < 4; nt++)
                MMA16816(acc[mt][nt], afr[0][mt], bfr[nt]);
    }
#undef TILE
#undef COMPUTE_TILE
#undef LOAD_A
#undef LOAD_B
#undef ISSUE_STAGE

    // ---- fused epilogue (no sync needed: registers + prologue smem) ----
    const int q = lane >> 2, r = lane & 3;
    const __half* sWcH = (const __half*)(smem + SMEM_WCH);
    const int i_img    = m_tile * 2 + wm;
    float* orow = out + (size_t)i_img * NDIM + n0;

#pragma unroll
    for (int nt = 0; nt < 4; nt++) {
        const int nA = wn * 32 + nt * 8 + r * 2;
        float s0 = 0.f, s1 = 0.f;
#pragma unroll
        for (int mt = 0; mt < 4; mt++) {
            const int clo = mt * 16 + q, chi = clo + 8;
            s0 += acc[mt][nt][0] * __half2float(sWcH[nA * WC_PITCH + clo])
                + acc[mt][nt][2] * __half2float(sWcH[nA * WC_PITCH + chi]);
            s1 += acc[mt][nt][1] * __half2float(sWcH[(nA + 1) * WC_PITCH + clo])
                + acc[mt][nt][3] * __half2float(sWcH[(nA + 1) * WC_PITCH + chi]);
        }
#pragma unroll
        for (int off = 4; off <= 16; off <<= 1) {
            s0 += __shfl_xor_sync(0xffffffffu, s0, off);
            s1 += __shfl_xor_sync(0xffffffffu, s1, off);
        }
        if (q == 0) {
            const float2 b2 = *(const float2*)(bias + n0 + nA);  // L2-resident
            float t0 = s0 + b2.x;
            float t1 = s1 + b2.y;
            float2 o;
            o.x = (t0 > 0.f) ? t0 : expm1f(t0);
            o.y = (t1 > 0.f) ? t1 : expm1f(t1);
            *(float2*)(orow + nA) = o;
        }
    }
}

// ---------------------------------------------------------------------------
extern "C" void kernel_launch(void* const* d_in, const int* in_sizes, int n_in,
                              void* d_out, int out_size) {
    const float* conv = (const float*)d_in[0];  // [256, 64, 36, 36]
    const float* Wc   = (const float*)d_in[1];  // [8192, 1, 64]
    const float* Wy   = (const float*)d_in[2];  // [8192, 1, 36]
    const float* Wx   = (const float*)d_in[3];  // [8192, 1, 36]
    const float* bias = (const float*)d_in[4];  // [8192]
    float* out = (float*)d_out;                 // [256, 8192]
    (void)in_sizes; (void)n_in; (void)out_size;

    cudaFuncSetAttribute(gemm_fused_kernel,
                         cudaFuncAttributeMaxDynamicSharedMemorySize, SMEM_TOTAL);

    probe_kernel<<<1, 1>>>();   // keeps ncu capture slot on the GEMM
    prepA_kernel<<<(MDIM * (KP / 8) + 255) / 256, 256>>>(conv);
    prepB_kernel<<<(NDIM * (KP / 8) + 255) / 256, 256>>>(Wy, Wx);
    gemm_fused_kernel<<<dim3(NDIM / BN, MDIM / BM), 512, SMEM_TOTAL>>>(Wc, bias, out);
}

// round 16
// speedup vs baseline: 1.0610x; 1.0610x over previous
#include <cuda_runtime.h>
#include <cuda_fp16.h>
#include <cstdint>

// ---------------------------------------------------------------------------
// out[i,n] = elu( sum_{c,y,x} conv[i,c,y,x] * Wc[n,c]*Wy[n,y]*Wx[n,x] + bias[n] )
// s[(i,c), n] = conv_flat[16384 x 1296] @ Wyx[8192 x 1296]^T   (fp16 HMMA, f32 acc)
// R16 = R14 (best: 8 warps 64x32, 2 CTA/SM, bulk+mbarrier ring, A-frag dbuf,
// partial last k-tile) + pipeline slack polish:
//  (a) empty-arrive moved to right after the tile's LAST LDSM (buffer dead)
//  (b) refill duty rotates across warps (RKT & 7) instead of always warp 0
//  (c) prepA/prepB merged into one launch
// tcgen05 unavailable: harness PTX target is sm_103 (no 'a' suffix).
// ---------------------------------------------------------------------------
#define MDIM 16384
#define NDIM 8192
#define KDIM 1296
#define KP   1344            // 21 * 64
#define NT   21
#define BM   128
#define BN   128
#define BK   64              // 64 halfs = 128B rows (SW128 atom)

#define A_TILE_BYTES (BM * BK * 2)                   // 16384
#define B_TILE_BYTES (BN * BK * 2)                   // 16384
#define STAGE_BYTES  (A_TILE_BYTES + B_TILE_BYTES)   // 32768
#define SMEM_BARS  (3 * STAGE_BYTES)                 // 98304: full[3]@+0, empty[3]@+24
#define SMEM_WCH   (SMEM_BARS + 64)                  // 98368: 128 x 66 half
#define WC_PITCH   66
#define SMEM_TOTAL (SMEM_WCH + BN * WC_PITCH * 2)    // 115264 (x2 CTA + rsv <= 233472)

#define A_GRANULES (MDIM * (KP / 8))                 // 2752512
#define B_GRANULES (NDIM * (KP / 8))                 // 1376256

// Pre-swizzled, tile-contiguous operand images (device globals: no-alloc rule)
__device__ __align__(1024) unsigned char g_A_t[(size_t)(MDIM / BM) * NT * A_TILE_BYTES]; // 44 MB
__device__ __align__(1024) unsigned char g_B_t[(size_t)(NDIM / BN) * NT * B_TILE_BYTES]; // 44 MB
__device__ int g_probe_sink;

// ---------------------------------------------------------------------------
__device__ __forceinline__ uint32_t smem_u32(const void* p) {
    uint32_t a;
    asm("{ .reg .u64 t; cvta.to.shared.u64 t, %1; cvt.u32.u64 %0, t; }" : "=r"(a) : "l"(p));
    return a;
}
__device__ __forceinline__ void bulk_ld(uint32_t dst, const void* src,
                                        uint32_t bytes, uint32_t mbar) {
    asm volatile(
        "cp.async.bulk.shared::cta.global.mbarrier::complete_tx::bytes [%0], [%1], %2, [%3];"
        :: "r"(dst), "l"(src), "r"(bytes), "r"(mbar) : "memory");
}
#define MBAR_INIT(a, n) \
    asm volatile("mbarrier.init.shared.b64 [%0], %1;" :: "r"(a), "r"((uint32_t)(n)) : "memory")
#define MBAR_ARRIVE(a) \
    asm volatile("mbarrier.arrive.shared.b64 _, [%0];" :: "r"(a) : "memory")
#define MBAR_EXPECT_TX(a, b) \
    asm volatile("mbarrier.arrive.expect_tx.shared.b64 _, [%0], %1;" \
                 :: "r"(a), "r"((uint32_t)(b)) : "memory")
#define MBAR_WAIT(a, ph) do {                                                        \
    asm volatile("{\n\t.reg .pred P;\n\t"                                            \
        "W%=:\n\t"                                                                   \
        "mbarrier.try_wait.parity.acquire.cta.shared::cta.b64 P, [%0], %1, 0x989680;\n\t" \
        "@P bra.uni D%=;\n\t bra.uni W%=;\n\tD%=:\n\t}"                              \
        :: "r"(a), "r"((uint32_t)(ph)) : "memory");                                  \
} while (0)

#define LDSM4(R0, R1, R2, R3, ADDR)                                            \
    asm volatile("ldmatrix.sync.aligned.m8n8.x4.shared.b16 {%0,%1,%2,%3}, [%4];" \
                 : "=r"(R0), "=r"(R1), "=r"(R2), "=r"(R3) : "r"(ADDR))

#define MMA16816(D, A, B)                                                      \
    asm volatile("mma.sync.aligned.m16n8k16.row.col.f32.f16.f16.f32 "          \
                 "{%0,%1,%2,%3}, {%4,%5,%6,%7}, {%8,%9}, {%0,%1,%2,%3};"       \
                 : "+f"((D)[0]), "+f"((D)[1]), "+f"((D)[2]), "+f"((D)[3])      \
                 : "r"((A)[0]), "r"((A)[1]), "r"((A)[2]), "r"((A)[3]),         \
                   "r"((B)[0]), "r"((B)[1]))

// ---------------------------------------------------------------------------
__global__ void probe_kernel() { g_probe_sink = 1; }   // aligns ncu capture

// ---------------------------------------------------------------------------
// Merged prep: A granules then B granules (one launch).
// A: conv fp32 -> fp16, tiled + SW128-swizzled, K padded to 1344.
// B: Wyx[n, y*36+x] = Wy[n,y]*Wx[n,x] -> fp16 tiled swizzled image.
// ---------------------------------------------------------------------------
__global__ void prep_kernel(const float* __restrict__ conv,
                            const float* __restrict__ Wy,
                            const float* __restrict__ Wx) {
    int g = blockIdx.x * 256 + threadIdx.x;
    if (g < A_GRANULES) {
        int m  = g / (KP / 8);
        int k0 = (g - m * (KP / 8)) * 8;
        __half2 h[4];
        if (k0 < KDIM) {   // 1296 = 162*8 -> granules fully in or out
            const float4* s = (const float4*)(conv + (size_t)m * KDIM + k0);
            float4 a = s[0], b = s[1];
            h[0] = __floats2half2_rn(a.x, a.y);
            h[1] = __floats2half2_rn(a.z, a.w);
            h[2] = __floats2half2_rn(b.x, b.y);
            h[3] = __floats2half2_rn(b.z, b.w);
        } else {
            h[0] = h[1] = h[2] = h[3] = __floats2half2_rn(0.f, 0.f);
        }
        int tm = m >> 7, row = m & 127, kt = k0 >> 6, kc = k0 & 63;
        uint32_t off = row * 128 + kc * 2;
        uint32_t sw  = off ^ ((off >> 3) & 0x70);
        *(uint4*)(g_A_t + (size_t)(tm * NT + kt) * A_TILE_BYTES + sw) = *(uint4*)h;
        return;
    }
    g -= A_GRANULES;
    if (g >= B_GRANULES) return;
    {
        int n  = g / (KP / 8);
        int k0 = (g - n * (KP / 8)) * 8;
        __half hv[8];
        if (k0 < KDIM) {
#pragma unroll
            for (int j = 0; j < 8; j++) {
                int k = k0 + j;
                int y = k / 36, x = k - y * 36;
                hv[j] = __float2half(Wy[n * 36 + y] * Wx[n * 36 + x]);
            }
        } else {
#pragma unroll
            for (int j = 0; j < 8; j++) hv[j] = __float2half(0.f);
        }
        int tn = n >> 7, row = n & 127, kt = k0 >> 6, kc = k0 & 63;
        uint32_t off = row * 128 + kc * 2;
        uint32_t sw  = off ^ ((off >> 3) & 0x70);
        *(uint4*)(g_B_t + (size_t)(tn * NT + kt) * B_TILE_BYTES + sw) = *(uint4*)hv;
    }
}

// ---------------------------------------------------------------------------
// Fused GEMM: 128x128x64 tiles, 8 warps (warp tile 64x32), mbarrier-ringed
// 3-stage cp.async.bulk pipeline, 2 CTAs/SM, A-frag double buffering,
// early empty-release, rotating refill warp, partial last k-tile,
// fused Wc(fp16 smem) reduce + bias(gmem) + ELU epilogue.
// ---------------------------------------------------------------------------
__global__ void __launch_bounds__(256, 2) gemm_fused_kernel(
    const float* __restrict__ Wc, const float* __restrict__ bias,
    float* __restrict__ out)
{
    extern __shared__ unsigned char smem[];
    const uint32_t sbase = smem_u32(smem);
    const int tid = threadIdx.x, lane = tid & 31, wid = tid >> 5;
    const int wm = wid >> 2, wn = wid & 3;       // 2 x 4 warp grid, tile 64x32
    const int m_tile = blockIdx.y, n_tile = blockIdx.x;
    const int n0 = n_tile * BN;

    const uint32_t FULLB  = sbase + SMEM_BARS;        // full[s]  at +s*8 (count 1, tx)
    const uint32_t EMPTYB = sbase + SMEM_BARS + 24;   // empty[s] at +s*8 (count 8)

    if (tid == 0) {
#pragma unroll
        for (int s = 0; s < 3; s++) {
            MBAR_INIT(FULLB + s * 8, 1);
            MBAR_INIT(EMPTYB + s * 8, 8);     // one arrive per warp (lane 0)
        }
    }

    // ---- Wc fp32 -> fp16 smem [n][c], pitch 66 ----
#pragma unroll
    for (int it = 0; it < 8; it++) {
        int idx = it * 256 + tid;              // 2048 float4 groups
        int n = idx >> 4, c4 = (idx & 15) * 4;
        float4 v = *(const float4*)(Wc + (size_t)(n0 + n) * 64 + c4);
        __half2* d = (__half2*)(smem + SMEM_WCH + (n * WC_PITCH + c4) * 2);
        d[0] = __floats2half2_rn(v.x, v.y);
        d[1] = __floats2half2_rn(v.z, v.w);
    }
    __syncthreads();   // mbarrier init + Wc visible (only sync in kernel)

#define ISSUE_STAGE(KT, BUF) do {                                              \
    uint32_t d_ = sbase + (BUF) * STAGE_BYTES;                                 \
    uint32_t f_ = FULLB + (BUF) * 8;                                           \
    MBAR_EXPECT_TX(f_, STAGE_BYTES);                                           \
    bulk_ld(d_, g_A_t + ((size_t)m_tile * NT + (KT)) * A_TILE_BYTES,           \
            A_TILE_BYTES, f_);                                                 \
    bulk_ld(d_ + A_TILE_BYTES,                                                 \
            g_B_t + ((size_t)n_tile * NT + (KT)) * B_TILE_BYTES,               \
            B_TILE_BYTES, f_);                                                 \
} while (0)

    if (tid == 0) {
        ISSUE_STAGE(0, 0);
        ISSUE_STAGE(1, 1);
        ISSUE_STAGE(2, 2);
    }

    // ---- merged per-lane ldmatrix constants (SW128) ----
    uint32_t aro[4];
#pragma unroll
    for (int mt = 0; mt < 4; mt++) {
        int r = wm * 64 + mt * 16 + (lane & 15);
        aro[mt] = (uint32_t)(r * 128) ^ ((r & 7) << 4);
    }
    const uint32_t a_colhi = (lane >> 4) * 16;
    const int brow = wn * 32 + lane;             // 32 B-rows per warp
    const uint32_t bro = (uint32_t)(A_TILE_BYTES + brow * 128) ^ ((brow & 7) << 4);

    float acc[4][4][4];
#pragma unroll
    for (int a = 0; a < 4; a++)
#pragma unroll
        for (int b = 0; b < 4; b++)
#pragma unroll
            for (int c = 0; c < 4; c++) acc[a][b][c] = 0.f;

    uint32_t afr[2][4][4];   // A fragments, ks-level double buffer
    uint32_t bfr[4][2];      // B fragments, single buffer

#define LOAD_A(KS, SB, FB) do {                                                \
    const uint32_t colA_ = (KS) * 32 + a_colhi;                                \
    _Pragma("unroll")                                                          \
    for (int mt_ = 0; mt_ < 4; mt_++)                                          \
        LDSM4(afr[FB][mt_][0], afr[FB][mt_][1],                                \
              afr[FB][mt_][2], afr[FB][mt_][3],                                \
              (SB) + (aro[mt_] ^ colA_));                                      \
} while (0)

#define LOAD_B(KS, SB) do {                                                    \
    const uint32_t colB_ = (KS) * 32;                                          \
    uint32_t r0_, r1_, r2_, r3_;                                               \
    LDSM4(r0_, r1_, r2_, r3_, (SB) + (bro ^ colB_));                           \
    bfr[0][0] = r0_; bfr[1][0] = r1_; bfr[2][0] = r2_; bfr[3][0] = r3_;        \
    LDSM4(r0_, r1_, r2_, r3_, (SB) + (bro ^ (colB_ + 16)));                    \
    bfr[0][1] = r0_; bfr[1][1] = r1_; bfr[2][1] = r2_; bfr[3][1] = r3_;        \
} while (0)

// Early empty-release: buffer is dead after the tile's LAST LDSM (ks=3 B-load)
#define COMPUTE_TILE(BUF) do {                                                 \
    const uint32_t sb_ = sbase + (BUF) * STAGE_BYTES;                          \
    LOAD_A(0, sb_, 0);                                                         \
    _Pragma("unroll")                                                          \
    for (int ks = 0; ks < 4; ks++) {                                           \
        LOAD_B(ks, sb_);                                                       \
        if (ks < 3) LOAD_A(ks + 1, sb_, (ks + 1) & 1);                         \
        else if (lane == 0) MBAR_ARRIVE(EMPTYB + (BUF) * 8);                   \
        const int cb_ = ks & 1;                                                \
        _Pragma("unroll")                                                      \
        for (int mt = 0; mt < 4; mt++)                                         \
            _Pragma("unroll")                                                  \
            for (int nt = 0; nt < 4; nt++)                                     \
                MMA16816(acc[mt][nt], afr[cb_][mt], bfr[nt]);                  \
    }                                                                          \
} while (0)

// TILE: wait full -> compute (releases empty early) -> rotating refill warp
#define TILE(BUF, FPAR, DOREFILL, RBUF, RPAR, RKT) do {                        \
    MBAR_WAIT(FULLB + (BUF) * 8, FPAR);                                        \
    COMPUTE_TILE(BUF);                                                         \
    if ((DOREFILL) && wid == ((RKT) & 7) && lane == 0) {                       \
        MBAR_WAIT(EMPTYB + (RBUF) * 8, RPAR);                                  \
        ISSUE_STAGE(RKT, RBUF);                                                \
    }                                                                          \
} while (0)

    // ---- mainloop: 20 full tiles + 1 partial (only ks=0 has real data) ----
    int ph = 0;
#pragma unroll 1
    for (int base = 0; base < 18; base += 3, ph ^= 1) {
        TILE(0, ph, (base > 0), 2, ph ^ 1, base + 2);
        TILE(1, ph, true,       0, ph,     base + 3);
        TILE(2, ph, true,       1, ph,     base + 4);
    }
    // peeled final group (base = 18, parity 0)
    TILE(0, 0, true, 2, 1, 20);     // tile 18; refills buf2 with tile 20
    TILE(1, 0, false, 0, 0, 0);     // tile 19; no refill
    {
        // tile 20 (buf 2, parity 0): only ks=0 (k-cols 1280-1295) is real.
        MBAR_WAIT(FULLB + 2 * 8, 0);
        const uint32_t sb_ = sbase + 2 * STAGE_BYTES;
        LOAD_A(0, sb_, 0);
        LOAD_B(0, sb_);
#pragma unroll
        for (int mt = 0; mt < 4; mt++)
#pragma unroll
            for (int nt = 0; nt < 4; nt++)
                MMA16816(acc[mt][nt], afr[0][mt], bfr[nt]);
    }
#undef TILE
#undef COMPUTE_TILE
#undef LOAD_A
#undef LOAD_B
#undef ISSUE_STAGE

    // ---- fused epilogue (no sync needed: registers + prologue smem) ----
    const int q = lane >> 2, r = lane & 3;
    const __half* sWcH = (const __half*)(smem + SMEM_WCH);
    const int i_img    = m_tile * 2 + wm;
    float* orow = out + (size_t)i_img * NDIM + n0;

#pragma unroll
    for (int nt = 0; nt < 4; nt++) {
        const int nA = wn * 32 + nt * 8 + r * 2;
        float s0 = 0.f, s1 = 0.f;
#pragma unroll
        for (int mt = 0; mt < 4; mt++) {
            const int clo = mt * 16 + q, chi = clo + 8;
            s0 += acc[mt][nt][0] * __half2float(sWcH[nA * WC_PITCH + clo])
                + acc[mt][nt][2] * __half2float(sWcH[nA * WC_PITCH + chi]);
            s1 += acc[mt][nt][1] * __half2float(sWcH[(nA + 1) * WC_PITCH + clo])
                + acc[mt][nt][3] * __half2float(sWcH[(nA + 1) * WC_PITCH + chi]);
        }
#pragma unroll
        for (int off = 4; off <= 16; off <<= 1) {
            s0 += __shfl_xor_sync(0xffffffffu, s0, off);
            s1 += __shfl_xor_sync(0xffffffffu, s1, off);
        }
        if (q == 0) {
            const float2 b2 = *(const float2*)(bias + n0 + nA);  // L2-resident
            float t0 = s0 + b2.x;
            float t1 = s1 + b2.y;
            float2 o;
            o.x = (t0 > 0.f) ? t0 : expm1f(t0);
            o.y = (t1 > 0.f) ? t1 : expm1f(t1);
            *(float2*)(orow + nA) = o;
        }
    }
}

// ---------------------------------------------------------------------------
extern "C" void kernel_launch(void* const* d_in, const int* in_sizes, int n_in,
                              void* d_out, int out_size) {
    const float* conv = (const float*)d_in[0];  // [256, 64, 36, 36]
    const float* Wc   = (const float*)d_in[1];  // [8192, 1, 64]
    const float* Wy   = (const float*)d_in[2];  // [8192, 1, 36]
    const float* Wx   = (const float*)d_in[3];  // [8192, 1, 36]
    const float* bias = (const float*)d_in[4];  // [8192]
    float* out = (float*)d_out;                 // [256, 8192]
    (void)in_sizes; (void)n_in; (void)out_size;

    cudaFuncSetAttribute(gemm_fused_kernel,
                         cudaFuncAttributeMaxDynamicSharedMemorySize, SMEM_TOTAL);

    probe_kernel<<<1, 1>>>();   // keeps ncu capture slot on the GEMM
    prep_kernel<<<(A_GRANULES + B_GRANULES + 255) / 256, 256>>>(conv, Wy, Wx);
    gemm_fused_kernel<<<dim3(NDIM / BN, MDIM / BM), 256, SMEM_TOTAL>>>(Wc, bias, out);
}